// round 4
// baseline (speedup 1.0000x reference)
#include <cuda_runtime.h>
#include <cuda_bf16.h>

#define KE_CONST 138.96f

__global__ void zero_out_kernel(float* __restrict__ out, int S) {
    int t = blockIdx.x * blockDim.x + threadIdx.x;
    if (t < S) out[t] = 0.0f;
}

__device__ __forceinline__ void process_pair(
    int i, int j, float d,
    const float* __restrict__ q,
    const int*   __restrict__ sys,
    float* __restrict__ sbin)
{
    if (i < j) {
        float qi = __ldg(q + i);
        float qj = __ldg(q + j);
        int   s  = __ldg(sys + i);

        float u = 2.0f * d;
        float phi = 0.0f;
        if (u < 1.0f) {
            // phi = 1 - 10u^3 + 15u^4 - 6u^5 = 1 + u^3 * (-10 + u*(15 - 6u))
            float u2 = u * u;
            float u3 = u2 * u;
            float p  = fmaf(u, fmaf(u, -6.0f, 15.0f), -10.0f);
            phi = fmaf(u3, p, 1.0f);
        }
        float inv_d   = __fdividef(1.0f, d);
        float inv_rs  = rsqrtf(fmaf(d, d, 1.0f));
        float chi     = fmaf(phi, inv_rs, (1.0f - phi) * inv_d);
        float e       = qi * qj * chi;
        atomicAdd(&sbin[s], e);
    }
}

__global__ void __launch_bounds__(256)
coulomb_kernel(const int*   __restrict__ pair,
               const float* __restrict__ dij,
               const float* __restrict__ q,
               const int*   __restrict__ sys,
               float*       __restrict__ out,
               int P, int S)
{
    extern __shared__ float sbin[];
    for (int s = threadIdx.x; s < S; s += blockDim.x) sbin[s] = 0.0f;
    __syncthreads();

    const int4*   pi4 = reinterpret_cast<const int4*>(pair);        // idx_i row
    const int4*   pj4 = reinterpret_cast<const int4*>(pair + P);    // idx_j row
    const float4* d4  = reinterpret_cast<const float4*>(dij);

    const int nvec   = P >> 2;
    const int stride = gridDim.x * blockDim.x;
    const int gtid   = blockIdx.x * blockDim.x + threadIdx.x;

    for (int v = gtid; v < nvec; v += stride) {
        int4   ii = __ldg(pi4 + v);
        int4   jj = __ldg(pj4 + v);
        float4 dd = __ldg(d4  + v);
        process_pair(ii.x, jj.x, dd.x, q, sys, sbin);
        process_pair(ii.y, jj.y, dd.y, q, sys, sbin);
        process_pair(ii.z, jj.z, dd.z, q, sys, sbin);
        process_pair(ii.w, jj.w, dd.w, q, sys, sbin);
    }

    // Scalar tail (P not divisible by 4 — not the case here, but cheap insurance)
    for (int p = (nvec << 2) + gtid; p < P; p += stride) {
        int   i = __ldg(pair + p);
        int   j = __ldg(pair + P + p);
        float d = __ldg(dij + p);
        process_pair(i, j, d, q, sys, sbin);
    }

    __syncthreads();

    // Flush per-CTA bins to global (scale by KE once here).
    for (int s = threadIdx.x; s < S; s += blockDim.x) {
        float v = sbin[s];
        if (v != 0.0f) atomicAdd(&out[s], v * KE_CONST);
    }
}

extern "C" void kernel_launch(void* const* d_in, const int* in_sizes, int n_in,
                              void* d_out, int out_size)
{
    const int*   pair = (const int*)  d_in[0];  // (2, P) int32
    const float* dij  = (const float*)d_in[1];  // (P, 1) float32
    const float* q    = (const float*)d_in[2];  // (N, 1) float32
    const int*   sys  = (const int*)  d_in[3];  // (N,)   int32
    float*       out  = (float*)d_out;

    const int P = in_sizes[1];      // element count of d_ij == number of pairs
    const int S = out_size;         // num_systems

    zero_out_kernel<<<(S + 255) / 256, 256>>>(out, S);

    const int threads = 256;
    const int blocks  = 1184;       // 8 CTAs/SM * 148 SMs
    const size_t smem = (size_t)S * sizeof(float);
    coulomb_kernel<<<blocks, threads, smem>>>(pair, dij, q, sys, out, P, S);
}

// round 6
// speedup vs baseline: 1.2881x; 1.2881x over previous
#include <cuda_runtime.h>
#include <cuda_bf16.h>

#define KE_CONST 138.96f

// Packed per-atom {charge, sys_idx-as-float-bits}. 1<<19 * 8B = 4 MB static
// scratch (allocation-free per harness rules). N in this problem is 262144.
#define QS_CAP (1 << 19)
__device__ float2 g_qs[QS_CAP];

__global__ void zero_out_kernel(float* __restrict__ out, int S) {
    int t = blockIdx.x * blockDim.x + threadIdx.x;
    if (t < S) out[t] = 0.0f;
}

__global__ void pack_qs_kernel(const float* __restrict__ q,
                               const int*   __restrict__ sys, int N) {
    int t = blockIdx.x * blockDim.x + threadIdx.x;
    if (t < N) g_qs[t] = make_float2(q[t], __int_as_float(sys[t]));
}

__device__ __forceinline__ float chi_fn(float d) {
    float u  = 2.0f * d;
    float u2 = u * u;
    float u3 = u2 * u;
    // phi = 1 + u^3 * (-10 + u*(15 - 6u)), clamped to 0 for u >= 1
    float p   = fmaf(u, fmaf(u, -6.0f, 15.0f), -10.0f);
    float phi = (u < 1.0f) ? fmaf(u3, p, 1.0f) : 0.0f;
    float inv_d  = __fdividef(1.0f, d);
    float inv_rs = rsqrtf(fmaf(d, d, 1.0f));
    return fmaf(phi, inv_rs, (1.0f - phi) * inv_d);
}

template <bool PACKED>
__device__ __forceinline__ void process_pair(
    int i, int j, float d,
    const float* __restrict__ q,
    const int*   __restrict__ sys,
    float* __restrict__ sbin)
{
    const bool m = (i < j);
    // Branchless predicated gathers: compiler emits @P LDG, keeping loads
    // batched for MLP instead of a divergent BSSY/BSYNC region.
    float qi, qj;
    int   s;
    if (PACKED) {
        float2 qs = m ? __ldg(&g_qs[i]) : make_float2(0.0f, 0.0f);  // one LDG.64
        qi = qs.x;
        s  = __float_as_int(qs.y);
    } else {
        qi = m ? __ldg(q + i)  : 0.0f;
        s  = m ? __ldg(sys + i) : 0;
    }
    qj = m ? __ldg(q + j) : 0.0f;

    float e = qi * qj * chi_fn(d);
    if (m) atomicAdd(&sbin[s], e);
}

template <bool PACKED>
__global__ void __launch_bounds__(256)
coulomb_kernel(const int*   __restrict__ pair,
               const float* __restrict__ dij,
               const float* __restrict__ q,
               const int*   __restrict__ sys,
               float*       __restrict__ out,
               int P, int S)
{
    extern __shared__ float sbin[];
    for (int s = threadIdx.x; s < S; s += blockDim.x) sbin[s] = 0.0f;
    __syncthreads();

    const int4*   pi4 = reinterpret_cast<const int4*>(pair);        // idx_i row
    const int4*   pj4 = reinterpret_cast<const int4*>(pair + P);    // idx_j row
    const float4* d4  = reinterpret_cast<const float4*>(dij);

    const int nvec   = P >> 2;
    const int stride = gridDim.x * blockDim.x;
    const int gtid   = blockIdx.x * blockDim.x + threadIdx.x;

    for (int v = gtid; v < nvec; v += stride) {
        // Streaming data is touched once: evict-first so it doesn't thrash
        // L2 against the hot 4 MB q/sys working set.
        int4   ii = __ldcs(pi4 + v);
        int4   jj = __ldcs(pj4 + v);
        float4 dd = __ldcs(d4  + v);
        process_pair<PACKED>(ii.x, jj.x, dd.x, q, sys, sbin);
        process_pair<PACKED>(ii.y, jj.y, dd.y, q, sys, sbin);
        process_pair<PACKED>(ii.z, jj.z, dd.z, q, sys, sbin);
        process_pair<PACKED>(ii.w, jj.w, dd.w, q, sys, sbin);
    }

    // Scalar tail (P % 4 != 0 insurance)
    for (int p = (nvec << 2) + gtid; p < P; p += stride) {
        int   i = __ldg(pair + p);
        int   j = __ldg(pair + P + p);
        float d = __ldg(dij + p);
        process_pair<PACKED>(i, j, d, q, sys, sbin);
    }

    __syncthreads();

    // Flush per-CTA bins to global (apply KE scale once here).
    for (int s = threadIdx.x; s < S; s += blockDim.x) {
        float v = sbin[s];
        if (v != 0.0f) atomicAdd(&out[s], v * KE_CONST);
    }
}

extern "C" void kernel_launch(void* const* d_in, const int* in_sizes, int n_in,
                              void* d_out, int out_size)
{
    const int*   pair = (const int*)  d_in[0];  // (2, P) int32
    const float* dij  = (const float*)d_in[1];  // (P, 1) float32
    const float* q    = (const float*)d_in[2];  // (N, 1) float32
    const int*   sys  = (const int*)  d_in[3];  // (N,)   int32
    float*       out  = (float*)d_out;

    const int P = in_sizes[1];      // number of pairs
    const int N = in_sizes[2];      // number of atoms
    const int S = out_size;         // num_systems

    zero_out_kernel<<<(S + 255) / 256, 256>>>(out, S);

    const int threads = 256;
    const int blocks  = 1184;       // 8 CTAs/SM * 148 SMs
    const size_t smem = (size_t)S * sizeof(float);

    if (N <= QS_CAP) {
        pack_qs_kernel<<<(N + 255) / 256, 256>>>(q, sys, N);
        coulomb_kernel<true><<<blocks, threads, smem>>>(pair, dij, q, sys, out, P, S);
    } else {
        coulomb_kernel<false><<<blocks, threads, smem>>>(pair, dij, q, sys, out, P, S);
    }
}